// round 9
// baseline (speedup 1.0000x reference)
#include <cuda_runtime.h>
#include <cuda_bf16.h>
#include <cstdint>

#define MDIM 1024
#define RANK 128
#define NBATCH 8
#define SEQ 512
#define NROWS (NBATCH * SEQ)          // 4096
#define KSPLIT 4
#define KS (MDIM / KSPLIT)            // 256
#define KC 64                         // k per smem chunk (gemm)
#define CHUNKS (KS / KC)              // 4

// Scratch (static __device__ globals; no allocations allowed).
__device__ float g_Tp[KSPLIT][NROWS * RANK];        // K-split partials, 8 MB
__device__ float g_norm[NROWS];                     // row squared norms
__device__ __nv_bfloat16 g_Bhi[RANK * MDIM];        // B^T hi: [n][k]
__device__ __nv_bfloat16 g_Blo[RANK * MDIM];        // B^T lo: [n][k]
__device__ __nv_bfloat16 g_Thi[NROWS * RANK];       // T hi: [row][k]
__device__ __nv_bfloat16 g_Tlo[NROWS * RANK];       // T lo: [row][k]

// ---------------- helpers ----------------
__device__ __forceinline__ uint32_t sm2u32(const void* p) {
    uint32_t a;
    asm("{ .reg .u64 t; cvta.to.shared.u64 t, %1; cvt.u32.u64 %0, t; }"
        : "=r"(a) : "l"(p));
    return a;
}
#define LDMX4(r, addr) \
    asm volatile("ldmatrix.sync.aligned.m8n8.x4.shared.b16 {%0,%1,%2,%3}, [%4];" \
        : "=r"((r)[0]), "=r"((r)[1]), "=r"((r)[2]), "=r"((r)[3]) : "r"(addr))

__device__ __forceinline__ void mma_bf16(float* c, const uint32_t* a,
                                         uint32_t b0, uint32_t b1) {
    asm volatile(
        "mma.sync.aligned.m16n8k16.row.col.f32.bf16.bf16.f32 "
        "{%0,%1,%2,%3}, {%4,%5,%6,%7}, {%8,%9}, {%0,%1,%2,%3};"
        : "+f"(c[0]), "+f"(c[1]), "+f"(c[2]), "+f"(c[3])
        : "r"(a[0]), "r"(a[1]), "r"(a[2]), "r"(a[3]), "r"(b0), "r"(b1));
}

// ---------------------------------------------------------------------------
// Kernel 0: transpose+split proj [1024,128] fp32 -> g_Bhi/g_Blo [128][1024] bf16
// ---------------------------------------------------------------------------
__global__ void convertB_kernel(const float* __restrict__ proj)
{
    __shared__ float tile[32][33];
    const int tx = threadIdx.x, ty = threadIdx.y;      // (32,8)
    const int k0 = blockIdx.x * 32, n0 = blockIdx.y * 32;
    #pragma unroll
    for (int i = 0; i < 4; i++)
        tile[ty + 8 * i][tx] = proj[(size_t)(k0 + ty + 8 * i) * RANK + n0 + tx];
    __syncthreads();
    #pragma unroll
    for (int i = 0; i < 4; i++) {
        int n = n0 + ty + 8 * i, k = k0 + tx;
        float v = tile[tx][ty + 8 * i];
        __nv_bfloat16 h = __float2bfloat16(v);
        __nv_bfloat16 l = __float2bfloat16(v - __bfloat162float(h));
        g_Bhi[(size_t)n * MDIM + k] = h;
        g_Blo[(size_t)n * MDIM + k] = l;
    }
}

// ---------------------------------------------------------------------------
// Kernel 1: mma.sync bf16-split GEMM. grid (KSPLIT, 64), 512 thr (16 warps).
// CTA: M=64, N=128, K=KS(256) in 4 chunks of 64. Warp grid 4(m)x4(n), tile 16x32.
// acc(f32) += Ahi*Bhi + Ahi*Blo + Alo*Bhi. smem rows padded to 144B.
// Register-pipelined: global prefetch of next chunk + ldmatrix double-buffer.
// ---------------------------------------------------------------------------
#define AHI_OFF 0
#define ALO_OFF 9216
#define BHI_OFF 18432
#define BLO_OFF 36864
#define SMEM_BYTES 55296

__global__ void __launch_bounds__(512) mma_gemm_kernel(const float* __restrict__ A)
{
    extern __shared__ char dsm[];
    const int tid  = threadIdx.x;
    const int wid  = tid >> 5, lane = tid & 31;
    const int split = blockIdx.x;
    const int mb    = blockIdx.y * 64;
    const int kbase = split * KS;

    const int warp_m = (wid & 3) * 16;
    const int warp_n = (wid >> 2) * 32;

    const uint32_t smem = sm2u32(dsm);
    const uint32_t a_off = (uint32_t)(warp_m + (lane & 15)) * 144 + (lane >> 4) * 16;
    const uint32_t aaddr_hi = smem + AHI_OFF + a_off;
    const uint32_t aaddr_lo = smem + ALO_OFF + a_off;
    const uint32_t b_noff = ((lane >> 3) & 1) * 8 + (lane & 7);
    const uint32_t b_off  = (uint32_t)(warp_n + b_noff) * 144 + (lane >> 4) * 16;
    const uint32_t baddr_hi = smem + BHI_OFF + b_off;
    const uint32_t baddr_lo = smem + BLO_OFF + b_off;

    // global-load indices (2 loads/thread per array)
    const int ar[2]  = { (tid + 0)   >> 4, (tid + 512) >> 4 };
    const int ak4[2] = { (tid + 0)   & 15, (tid + 512) & 15 };
    const int bn[2]  = { (tid + 0)   >> 3, (tid + 512) >> 3 };
    const int bg[2]  = { (tid + 0)   & 7,  (tid + 512) & 7  };

    float acc[4][4];
    #pragma unroll
    for (int i = 0; i < 4; i++)
        #pragma unroll
        for (int j = 0; j < 4; j++) acc[i][j] = 0.0f;

    // prefetch registers for chunk 0
    float4 pa[2];
    uint4 pbh[2], pbl[2];
    #pragma unroll
    for (int t = 0; t < 2; t++) {
        pa[t] = *(const float4*)&A[(size_t)(mb + ar[t]) * MDIM + kbase + ak4[t] * 4];
        size_t src = (size_t)bn[t] * MDIM + kbase + bg[t] * 8;
        pbh[t] = *(const uint4*)&g_Bhi[src];
        pbl[t] = *(const uint4*)&g_Blo[src];
    }

    for (int c = 0; c < CHUNKS; c++) {
        if (c) __syncthreads();

        // commit prefetched chunk to smem (A converted fp32 -> bf16 hi/lo)
        #pragma unroll
        for (int t = 0; t < 2; t++) {
            float4 v = pa[t];
            __nv_bfloat16 h0 = __float2bfloat16(v.x);
            __nv_bfloat16 h1 = __float2bfloat16(v.y);
            __nv_bfloat16 h2 = __float2bfloat16(v.z);
            __nv_bfloat16 h3 = __float2bfloat16(v.w);
            union { __nv_bfloat162 b2[2]; unsigned long long u; } ph, pl;
            ph.b2[0] = __nv_bfloat162(h0, h1);
            ph.b2[1] = __nv_bfloat162(h2, h3);
            pl.b2[0] = __nv_bfloat162(__float2bfloat16(v.x - __bfloat162float(h0)),
                                      __float2bfloat16(v.y - __bfloat162float(h1)));
            pl.b2[1] = __nv_bfloat162(__float2bfloat16(v.z - __bfloat162float(h2)),
                                      __float2bfloat16(v.w - __bfloat162float(h3)));
            *(unsigned long long*)(dsm + AHI_OFF + ar[t] * 144 + ak4[t] * 8) = ph.u;
            *(unsigned long long*)(dsm + ALO_OFF + ar[t] * 144 + ak4[t] * 8) = pl.u;
            *(uint4*)(dsm + BHI_OFF + bn[t] * 144 + bg[t] * 16) = pbh[t];
            *(uint4*)(dsm + BLO_OFF + bn[t] * 144 + bg[t] * 16) = pbl[t];
        }
        __syncthreads();

        // issue global prefetch for next chunk (overlaps with MMA phase)
        if (c + 1 < CHUNKS) {
            const int kn = kbase + (c + 1) * KC;
            #pragma unroll
            for (int t = 0; t < 2; t++) {
                pa[t] = *(const float4*)&A[(size_t)(mb + ar[t]) * MDIM + kn + ak4[t] * 4];
                size_t src = (size_t)bn[t] * MDIM + kn + bg[t] * 8;
                pbh[t] = *(const uint4*)&g_Bhi[src];
                pbl[t] = *(const uint4*)&g_Blo[src];
            }
        }

        // ldmatrix double-buffered over kk = 0..3
        uint32_t ah[2][4], al[2][4], bh[2][2][4], bl[2][2][4];
#define G_LOAD(buf, kk) do {                                          \
        LDMX4(ah[buf], aaddr_hi + (kk) * 32);                         \
        LDMX4(al[buf], aaddr_lo + (kk) * 32);                         \
        LDMX4(bh[buf][0], baddr_hi + (kk) * 32);                      \
        LDMX4(bh[buf][1], baddr_hi + 16 * 144 + (kk) * 32);           \
        LDMX4(bl[buf][0], baddr_lo + (kk) * 32);                      \
        LDMX4(bl[buf][1], baddr_lo + 16 * 144 + (kk) * 32);           \
    } while (0)

        G_LOAD(0, 0);
        #pragma unroll
        for (int kk = 0; kk < 4; kk++) {
            const int cur = kk & 1;
            if (kk + 1 < 4) G_LOAD(cur ^ 1, kk + 1);
            #pragma unroll
            for (int nn = 0; nn < 2; nn++) {
                float* c0 = acc[nn * 2];
                float* c1 = acc[nn * 2 + 1];
                mma_bf16(c0, ah[cur], bh[cur][nn][0], bh[cur][nn][2]);
                mma_bf16(c0, ah[cur], bl[cur][nn][0], bl[cur][nn][2]);
                mma_bf16(c0, al[cur], bh[cur][nn][0], bh[cur][nn][2]);
                mma_bf16(c1, ah[cur], bh[cur][nn][1], bh[cur][nn][3]);
                mma_bf16(c1, ah[cur], bl[cur][nn][1], bl[cur][nn][3]);
                mma_bf16(c1, al[cur], bh[cur][nn][1], bh[cur][nn][3]);
            }
        }
#undef G_LOAD
    }

    float* __restrict__ P = g_Tp[split];
    const int m0 = mb + warp_m + (lane >> 2);
    #pragma unroll
    for (int ch = 0; ch < 4; ch++) {
        int n = warp_n + ch * 8 + (lane & 3) * 2;
        *(float2*)&P[(size_t)m0 * RANK + n] = make_float2(acc[ch][0], acc[ch][1]);
        *(float2*)&P[(size_t)(m0 + 8) * RANK + n] = make_float2(acc[ch][2], acc[ch][3]);
    }
}

// ---------------------------------------------------------------------------
// Kernel 2: combine K-split partials -> bf16 hi/lo T + per-row squared norms.
// ---------------------------------------------------------------------------
__global__ void __launch_bounds__(256) combine_kernel()
{
    int idx = blockIdx.x * 256 + threadIdx.x;      // float4 index
    const float4* p0 = (const float4*)g_Tp[0];
    const float4* p1 = (const float4*)g_Tp[1];
    const float4* p2 = (const float4*)g_Tp[2];
    const float4* p3 = (const float4*)g_Tp[3];
    float4 a = p0[idx], b = p1[idx], c = p2[idx], d = p3[idx];
    float4 v;
    v.x = a.x + b.x + c.x + d.x;
    v.y = a.y + b.y + c.y + d.y;
    v.z = a.z + b.z + c.z + d.z;
    v.w = a.w + b.w + c.w + d.w;

    __nv_bfloat16 h0 = __float2bfloat16(v.x);
    __nv_bfloat16 h1 = __float2bfloat16(v.y);
    __nv_bfloat16 h2 = __float2bfloat16(v.z);
    __nv_bfloat16 h3 = __float2bfloat16(v.w);
    union { __nv_bfloat162 b2[2]; uint2 u; } ph, pl;
    ph.b2[0] = __nv_bfloat162(h0, h1);
    ph.b2[1] = __nv_bfloat162(h2, h3);
    pl.b2[0] = __nv_bfloat162(__float2bfloat16(v.x - __bfloat162float(h0)),
                              __float2bfloat16(v.y - __bfloat162float(h1)));
    pl.b2[1] = __nv_bfloat162(__float2bfloat16(v.z - __bfloat162float(h2)),
                              __float2bfloat16(v.w - __bfloat162float(h3)));
    *(uint2*)&g_Thi[(size_t)idx * 4] = ph.u;
    *(uint2*)&g_Tlo[(size_t)idx * 4] = pl.u;

    float sq = v.x * v.x + v.y * v.y + v.z * v.z + v.w * v.w;
    #pragma unroll
    for (int off = 16; off > 0; off >>= 1)
        sq += __shfl_down_sync(0xffffffffu, sq, off);
    if ((threadIdx.x & 31) == 0)
        g_norm[idx >> 5] = sq;                     // 32 float4 per row
}

// ---------------------------------------------------------------------------
// Kernel 3: pdist via mma.sync bf16 hi/lo Gram.
// CTA: 128(i) x 128(j) tile, full K=128 in smem. grid (4,4,8), 512 thr.
// Warp grid 4(m)x4(n); warp tile 32x32. ldmatrix double-buffered over kk.
// d(i,j) = n_i + n_j - 2*(Ihi·Jhi + Ihi·Jlo + Ilo·Jhi); diag forced to 0.
// smem rows 272B; 272 % 128 = 16 -> ldmatrix conflict-free.
// ---------------------------------------------------------------------------
#define PD_IH 0
#define PD_IL 34816
#define PD_JH 69632
#define PD_JL 104448
#define PD_SMEM 139264
#define PD_STR 272

__global__ void __launch_bounds__(512) pdist_mma_kernel(float* __restrict__ out)
{
    extern __shared__ char dsm[];
    const int tid  = threadIdx.x;
    const int wid  = tid >> 5, lane = tid & 31;
    const int bj = blockIdx.x, bi = blockIdx.y, b = blockIdx.z;
    const int i0 = bi * 128, j0 = bj * 128;
    const bool diag = (bi == bj);

    const __nv_bfloat16* __restrict__ TH = g_Thi + (size_t)b * SEQ * RANK;
    const __nv_bfloat16* __restrict__ TL = g_Tlo + (size_t)b * SEQ * RANK;

    // Stage I (and J if off-diagonal): 128 rows x 128 k bf16, hi+lo.
    #pragma unroll
    for (int t = 0; t < 4; t++) {
        int idx = tid + t * 512;          // 0..2047
        int r = idx >> 4, g = idx & 15;
        size_t si = (size_t)(i0 + r) * RANK + g * 8;
        *(uint4*)(dsm + PD_IH + r * PD_STR + g * 16) = *(const uint4*)&TH[si];
        *(uint4*)(dsm + PD_IL + r * PD_STR + g * 16) = *(const uint4*)&TL[si];
        if (!diag) {
            size_t sj = (size_t)(j0 + r) * RANK + g * 8;
            *(uint4*)(dsm + PD_JH + r * PD_STR + g * 16) = *(const uint4*)&TH[sj];
            *(uint4*)(dsm + PD_JL + r * PD_STR + g * 16) = *(const uint4*)&TL[sj];
        }
    }
    __syncthreads();

    const int warp_m = (wid & 3) * 32;
    const int warp_n = (wid >> 2) * 32;
    const uint32_t smem = sm2u32(dsm);

    const uint32_t ia_off = (uint32_t)(warp_m + (lane & 15)) * PD_STR + (lane >> 4) * 16;
    const uint32_t iaddr_h = smem + PD_IH + ia_off;
    const uint32_t iaddr_l = smem + PD_IL + ia_off;
    const uint32_t j_noff = ((lane >> 3) & 1) * 8 + (lane & 7);
    const uint32_t ja_off = (uint32_t)(warp_n + j_noff) * PD_STR + (lane >> 4) * 16;
    const uint32_t jaddr_h = smem + (diag ? PD_IH : PD_JH) + ja_off;
    const uint32_t jaddr_l = smem + (diag ? PD_IL : PD_JL) + ja_off;

    float acc[2][4][4];
    #pragma unroll
    for (int mf = 0; mf < 2; mf++)
        #pragma unroll
        for (int i = 0; i < 4; i++)
            #pragma unroll
            for (int j = 0; j < 4; j++) acc[mf][i][j] = 0.0f;

    // ldmatrix double-buffered over kk = 0..7
    uint32_t ih[2][2][4], il[2][2][4], jh[2][2][4], jl[2][2][4];
#define PD_LOAD(buf, kk) do {                                       \
    LDMX4(ih[buf][0], iaddr_h + (kk) * 32);                         \
    LDMX4(ih[buf][1], iaddr_h + 16 * PD_STR + (kk) * 32);           \
    LDMX4(il[buf][0], iaddr_l + (kk) * 32);                         \
    LDMX4(il[buf][1], iaddr_l + 16 * PD_STR + (kk) * 32);           \
    LDMX4(jh[buf][0], jaddr_h + (kk) * 32);                         \
    LDMX4(jh[buf][1], jaddr_h + 16 * PD_STR + (kk) * 32);           \
    LDMX4(jl[buf][0], jaddr_l + (kk) * 32);                         \
    LDMX4(jl[buf][1], jaddr_l + 16 * PD_STR + (kk) * 32);           \
} while (0)

    PD_LOAD(0, 0);
    #pragma unroll
    for (int kk = 0; kk < 8; kk++) {
        const int cur = kk & 1;
        if (kk + 1 < 8) PD_LOAD(cur ^ 1, kk + 1);
        #pragma unroll
        for (int nn = 0; nn < 2; nn++) {
            #pragma unroll
            for (int mf = 0; mf < 2; mf++) {
                float* c0 = acc[mf][nn * 2];
                float* c1 = acc[mf][nn * 2 + 1];
                mma_bf16(c0, ih[cur][mf], jh[cur][nn][0], jh[cur][nn][2]);
                mma_bf16(c0, ih[cur][mf], jl[cur][nn][0], jl[cur][nn][2]);
                mma_bf16(c0, il[cur][mf], jh[cur][nn][0], jh[cur][nn][2]);
                mma_bf16(c1, ih[cur][mf], jh[cur][nn][1], jh[cur][nn][3]);
                mma_bf16(c1, ih[cur][mf], jl[cur][nn][1], jl[cur][nn][3]);
                mma_bf16(c1, il[cur][mf], jh[cur][nn][1], jh[cur][nn][3]);
            }
        }
    }
#undef PD_LOAD

    // Epilogue: d = n_i + n_j - 2*dot; exact 0 on diagonal.
    const float* __restrict__ nb = g_norm + (size_t)b * SEQ;
    float* __restrict__ ob = out + (size_t)b * SEQ * SEQ;
    #pragma unroll
    for (int mf = 0; mf < 2; mf++) {
        int gi = i0 + warp_m + mf * 16 + (lane >> 2);
        float ni0 = nb[gi], ni1 = nb[gi + 8];
        #pragma unroll
        for (int ch = 0; ch < 4; ch++) {
            int gj = j0 + warp_n + ch * 8 + (lane & 3) * 2;
            float nj0 = nb[gj], nj1 = nb[gj + 1];
            float* a = acc[mf][ch];
            float v00 = ni0 + nj0 - 2.0f * a[0];
            float v01 = ni0 + nj1 - 2.0f * a[1];
            float v10 = ni1 + nj0 - 2.0f * a[2];
            float v11 = ni1 + nj1 - 2.0f * a[3];
            if (diag) {
                if (gi == gj) v00 = 0.0f;
                if (gi == gj + 1) v01 = 0.0f;
                if (gi + 8 == gj) v10 = 0.0f;
                if (gi + 8 == gj + 1) v11 = 0.0f;
            }
            *(float2*)&ob[(size_t)gi * SEQ + gj] = make_float2(v00, v01);
            *(float2*)&ob[(size_t)(gi + 8) * SEQ + gj] = make_float2(v10, v11);
        }
    }
}

extern "C" void kernel_launch(void* const* d_in, const int* in_sizes, int n_in,
                              void* d_out, int out_size)
{
    const float* batch = (const float*)d_in[0];   // [8,512,1024]
    const float* proj  = (const float*)d_in[1];   // [1024,128]
    float* out = (float*)d_out;                   // [8,512,512]

    // Idempotent; first call happens on the correctness run (outside capture).
    cudaFuncSetAttribute(mma_gemm_kernel,
                         cudaFuncAttributeMaxDynamicSharedMemorySize, SMEM_BYTES);
    cudaFuncSetAttribute(pdist_mma_kernel,
                         cudaFuncAttributeMaxDynamicSharedMemorySize, PD_SMEM);

    convertB_kernel<<<dim3(MDIM / 32, RANK / 32), dim3(32, 8)>>>(proj);
    mma_gemm_kernel<<<dim3(KSPLIT, NROWS / 64), 512, SMEM_BYTES>>>(batch);
    combine_kernel<<<NROWS * RANK / 4 / 256, 256>>>();
    pdist_mma_kernel<<<dim3(4, 4, 8), 512, PD_SMEM>>>(out);
}

// round 10
// speedup vs baseline: 1.2430x; 1.2430x over previous
#include <cuda_runtime.h>
#include <cuda_fp16.h>
#include <cstdint>

#define MDIM 1024
#define RANK 128
#define NBATCH 8
#define SEQ 512
#define NROWS (NBATCH * SEQ)          // 4096
#define KSPLIT 4
#define KS (MDIM / KSPLIT)            // 256
#define KC 64                         // k per smem chunk (gemm)
#define CHUNKS (KS / KC)              // 4

// Scratch (static __device__ globals; no allocations allowed).
__device__ float g_Tp[KSPLIT][NROWS * RANK];   // K-split partials, 8 MB
__device__ float g_norm[NROWS];                // row squared norms (fp32 exact)
__device__ __half g_Bhi[RANK * MDIM];          // B^T hi: [n][k] fp16
__device__ __half g_Blo[RANK * MDIM];          // B^T lo: [n][k] fp16 (residual)
__device__ __half g_Th[NROWS * RANK];          // T: [row][k] fp16 (single)

// ---------------- helpers ----------------
__device__ __forceinline__ uint32_t sm2u32(const void* p) {
    uint32_t a;
    asm("{ .reg .u64 t; cvta.to.shared.u64 t, %1; cvt.u32.u64 %0, t; }"
        : "=r"(a) : "l"(p));
    return a;
}
#define LDMX4(r, addr) \
    asm volatile("ldmatrix.sync.aligned.m8n8.x4.shared.b16 {%0,%1,%2,%3}, [%4];" \
        : "=r"((r)[0]), "=r"((r)[1]), "=r"((r)[2]), "=r"((r)[3]) : "r"(addr))

__device__ __forceinline__ void mma_f16(float* c, const uint32_t* a,
                                        uint32_t b0, uint32_t b1) {
    asm volatile(
        "mma.sync.aligned.m16n8k16.row.col.f32.f16.f16.f32 "
        "{%0,%1,%2,%3}, {%4,%5,%6,%7}, {%8,%9}, {%0,%1,%2,%3};"
        : "+f"(c[0]), "+f"(c[1]), "+f"(c[2]), "+f"(c[3])
        : "r"(a[0]), "r"(a[1]), "r"(a[2]), "r"(a[3]), "r"(b0), "r"(b1));
}

// ---------------------------------------------------------------------------
// Kernel 0: transpose+split proj [1024,128] fp32 -> g_Bhi/g_Blo [128][1024] fp16
// ---------------------------------------------------------------------------
__global__ void convertB_kernel(const float* __restrict__ proj)
{
    __shared__ float tile[32][33];
    const int tx = threadIdx.x, ty = threadIdx.y;      // (32,8)
    const int k0 = blockIdx.x * 32, n0 = blockIdx.y * 32;
    #pragma unroll
    for (int i = 0; i < 4; i++)
        tile[ty + 8 * i][tx] = proj[(size_t)(k0 + ty + 8 * i) * RANK + n0 + tx];
    __syncthreads();
    #pragma unroll
    for (int i = 0; i < 4; i++) {
        int n = n0 + ty + 8 * i, k = k0 + tx;
        float v = tile[tx][ty + 8 * i];
        __half h = __float2half_rn(v);
        __half l = __float2half_rn(v - __half2float(h));
        g_Bhi[(size_t)n * MDIM + k] = h;
        g_Blo[(size_t)n * MDIM + k] = l;
    }
}

// ---------------------------------------------------------------------------
// Kernel 1: mma.sync fp16 GEMM: acc(f32) += A(fp16) * (Bhi + Blo).
// grid (KSPLIT, 64), 512 thr (16 warps). CTA: M=64, N=128, K=KS(256), 4 chunks.
// Warp grid 4(m)x4(n), warp tile 16x32. smem rows padded to 144B.
// ---------------------------------------------------------------------------
#define AH_OFF 0
#define BH_OFF 9216
#define BL_OFF 27648
#define SMEM_BYTES 46080

__global__ void __launch_bounds__(512) mma_gemm_kernel(const float* __restrict__ A)
{
    extern __shared__ char dsm[];
    const int tid  = threadIdx.x;
    const int wid  = tid >> 5, lane = tid & 31;
    const int split = blockIdx.x;
    const int mb    = blockIdx.y * 64;
    const int kbase = split * KS;

    const int warp_m = (wid & 3) * 16;
    const int warp_n = (wid >> 2) * 32;

    const uint32_t smem = sm2u32(dsm);
    const uint32_t a_off = (uint32_t)(warp_m + (lane & 15)) * 144 + (lane >> 4) * 16;
    const uint32_t aaddr = smem + AH_OFF + a_off;
    const uint32_t b_noff = ((lane >> 3) & 1) * 8 + (lane & 7);
    const uint32_t b_off  = (uint32_t)(warp_n + b_noff) * 144 + (lane >> 4) * 16;
    const uint32_t baddr_h = smem + BH_OFF + b_off;
    const uint32_t baddr_l = smem + BL_OFF + b_off;

    float acc[4][4];
    #pragma unroll
    for (int i = 0; i < 4; i++)
        #pragma unroll
        for (int j = 0; j < 4; j++) acc[i][j] = 0.0f;

    for (int c = 0; c < CHUNKS; c++) {
        if (c) __syncthreads();

        // A chunk [64][64] fp32 -> fp16 into smem (1024 float4, 2/thread)
        #pragma unroll
        for (int t = 0; t < 2; t++) {
            int idx = tid + t * 512;
            int r = idx >> 4, k4 = idx & 15;
            float4 v = *(const float4*)&A[(size_t)(mb + r) * MDIM + kbase + c * KC + k4 * 4];
            union { __half2 h2[2]; unsigned long long u; } ph;
            ph.h2[0] = __halves2half2(__float2half_rn(v.x), __float2half_rn(v.y));
            ph.h2[1] = __halves2half2(__float2half_rn(v.z), __float2half_rn(v.w));
            *(unsigned long long*)(dsm + AH_OFF + r * 144 + k4 * 8) = ph.u;
        }
        // B chunk [128][64] fp16 hi/lo (1024 uint4, 2/thread)
        #pragma unroll
        for (int t = 0; t < 2; t++) {
            int idx = tid + t * 512;
            int n = idx >> 3, g = idx & 7;
            size_t src = (size_t)n * MDIM + kbase + c * KC + g * 8;
            *(uint4*)(dsm + BH_OFF + n * 144 + g * 16) = *(const uint4*)&g_Bhi[src];
            *(uint4*)(dsm + BL_OFF + n * 144 + g * 16) = *(const uint4*)&g_Blo[src];
        }
        __syncthreads();

        #pragma unroll
        for (int kk = 0; kk < 4; kk++) {
            uint32_t ah[4];
            LDMX4(ah, aaddr + kk * 32);
            #pragma unroll
            for (int nn = 0; nn < 2; nn++) {
                uint32_t bh[4], bl[4];
                LDMX4(bh, baddr_h + nn * 16 * 144 + kk * 32);
                LDMX4(bl, baddr_l + nn * 16 * 144 + kk * 32);
                float* c0 = acc[nn * 2];
                float* c1 = acc[nn * 2 + 1];
                mma_f16(c0, ah, bh[0], bh[2]);
                mma_f16(c0, ah, bl[0], bl[2]);
                mma_f16(c1, ah, bh[1], bh[3]);
                mma_f16(c1, ah, bl[1], bl[3]);
            }
        }
    }

    float* __restrict__ P = g_Tp[split];
    const int m0 = mb + warp_m + (lane >> 2);
    #pragma unroll
    for (int ch = 0; ch < 4; ch++) {
        int n = warp_n + ch * 8 + (lane & 3) * 2;
        *(float2*)&P[(size_t)m0 * RANK + n] = make_float2(acc[ch][0], acc[ch][1]);
        *(float2*)&P[(size_t)(m0 + 8) * RANK + n] = make_float2(acc[ch][2], acc[ch][3]);
    }
}

// ---------------------------------------------------------------------------
// Kernel 2: combine K-split partials -> fp16 T + fp32 per-row squared norms.
// ---------------------------------------------------------------------------
__global__ void __launch_bounds__(256) combine_kernel()
{
    int idx = blockIdx.x * 256 + threadIdx.x;      // float4 index
    const float4* p0 = (const float4*)g_Tp[0];
    const float4* p1 = (const float4*)g_Tp[1];
    const float4* p2 = (const float4*)g_Tp[2];
    const float4* p3 = (const float4*)g_Tp[3];
    float4 a = p0[idx], b = p1[idx], c = p2[idx], d = p3[idx];
    float4 v;
    v.x = a.x + b.x + c.x + d.x;
    v.y = a.y + b.y + c.y + d.y;
    v.z = a.z + b.z + c.z + d.z;
    v.w = a.w + b.w + c.w + d.w;

    union { __half2 h2[2]; uint2 u; } ph;
    ph.h2[0] = __halves2half2(__float2half_rn(v.x), __float2half_rn(v.y));
    ph.h2[1] = __halves2half2(__float2half_rn(v.z), __float2half_rn(v.w));
    *(uint2*)&g_Th[(size_t)idx * 4] = ph.u;

    float sq = v.x * v.x + v.y * v.y + v.z * v.z + v.w * v.w;
    #pragma unroll
    for (int off = 16; off > 0; off >>= 1)
        sq += __shfl_down_sync(0xffffffffu, sq, off);
    if ((threadIdx.x & 31) == 0)
        g_norm[idx >> 5] = sq;                     // 32 float4 per row
}

// ---------------------------------------------------------------------------
// Kernel 3: pdist via single-pass fp16 mma.sync Gram.
// CTA: 128(i) x 128(j) tile, full K=128 in smem. grid (4,4,8), 512 thr.
// Warp grid 4(m)x4(n); warp tile 32x32.
// d(i,j) = n_i + n_j - 2*(I·J); diag forced to 0.
// smem rows 272B; 272 % 128 = 16 -> ldmatrix conflict-free.
// ---------------------------------------------------------------------------
#define PD_I 0
#define PD_J 34816
#define PD_SMEM 69632
#define PD_STR 272

__global__ void __launch_bounds__(512) pdist_mma_kernel(float* __restrict__ out)
{
    extern __shared__ char dsm[];
    const int tid  = threadIdx.x;
    const int wid  = tid >> 5, lane = tid & 31;
    const int bj = blockIdx.x, bi = blockIdx.y, b = blockIdx.z;
    const int i0 = bi * 128, j0 = bj * 128;
    const bool diag = (bi == bj);

    const __half* __restrict__ TH = g_Th + (size_t)b * SEQ * RANK;

    // Stage I (and J if off-diagonal): 128 rows x 128 k fp16.
    #pragma unroll
    for (int t = 0; t < 4; t++) {
        int idx = tid + t * 512;          // 0..2047
        int r = idx >> 4, g = idx & 15;
        size_t si = (size_t)(i0 + r) * RANK + g * 8;
        *(uint4*)(dsm + PD_I + r * PD_STR + g * 16) = *(const uint4*)&TH[si];
        if (!diag) {
            size_t sj = (size_t)(j0 + r) * RANK + g * 8;
            *(uint4*)(dsm + PD_J + r * PD_STR + g * 16) = *(const uint4*)&TH[sj];
        }
    }
    __syncthreads();

    const int warp_m = (wid & 3) * 32;
    const int warp_n = (wid >> 2) * 32;
    const uint32_t smem = sm2u32(dsm);

    const uint32_t ia_off = (uint32_t)(warp_m + (lane & 15)) * PD_STR + (lane >> 4) * 16;
    const uint32_t iaddr = smem + PD_I + ia_off;
    const uint32_t j_noff = ((lane >> 3) & 1) * 8 + (lane & 7);
    const uint32_t ja_off = (uint32_t)(warp_n + j_noff) * PD_STR + (lane >> 4) * 16;
    const uint32_t jaddr = smem + (diag ? PD_I : PD_J) + ja_off;

    float acc[2][4][4];
    #pragma unroll
    for (int mf = 0; mf < 2; mf++)
        #pragma unroll
        for (int i = 0; i < 4; i++)
            #pragma unroll
            for (int j = 0; j < 4; j++) acc[mf][i][j] = 0.0f;

    #pragma unroll
    for (int kk = 0; kk < 8; kk++) {
        uint32_t ih[2][4];
        LDMX4(ih[0], iaddr + kk * 32);
        LDMX4(ih[1], iaddr + 16 * PD_STR + kk * 32);
        #pragma unroll
        for (int nn = 0; nn < 2; nn++) {
            uint32_t jh[4];
            LDMX4(jh, jaddr + nn * 16 * PD_STR + kk * 32);
            #pragma unroll
            for (int mf = 0; mf < 2; mf++) {
                float* c0 = acc[mf][nn * 2];
                float* c1 = acc[mf][nn * 2 + 1];
                mma_f16(c0, ih[mf], jh[0], jh[2]);
                mma_f16(c1, ih[mf], jh[1], jh[3]);
            }
        }
    }

    // Epilogue: d = n_i + n_j - 2*dot; exact 0 on diagonal.
    const float* __restrict__ nb = g_norm + (size_t)b * SEQ;
    float* __restrict__ ob = out + (size_t)b * SEQ * SEQ;
    #pragma unroll
    for (int mf = 0; mf < 2; mf++) {
        int gi = i0 + warp_m + mf * 16 + (lane >> 2);
        float ni0 = nb[gi], ni1 = nb[gi + 8];
        #pragma unroll
        for (int ch = 0; ch < 4; ch++) {
            int gj = j0 + warp_n + ch * 8 + (lane & 3) * 2;
            float nj0 = nb[gj], nj1 = nb[gj + 1];
            float* a = acc[mf][ch];
            float v00 = ni0 + nj0 - 2.0f * a[0];
            float v01 = ni0 + nj1 - 2.0f * a[1];
            float v10 = ni1 + nj0 - 2.0f * a[2];
            float v11 = ni1 + nj1 - 2.0f * a[3];
            if (diag) {
                if (gi == gj) v00 = 0.0f;
                if (gi == gj + 1) v01 = 0.0f;
                if (gi + 8 == gj) v10 = 0.0f;
                if (gi + 8 == gj + 1) v11 = 0.0f;
            }
            *(float2*)&ob[(size_t)gi * SEQ + gj] = make_float2(v00, v01);
            *(float2*)&ob[(size_t)(gi + 8) * SEQ + gj] = make_float2(v10, v11);
        }
    }
}

extern "C" void kernel_launch(void* const* d_in, const int* in_sizes, int n_in,
                              void* d_out, int out_size)
{
    const float* batch = (const float*)d_in[0];   // [8,512,1024]
    const float* proj  = (const float*)d_in[1];   // [1024,128]
    float* out = (float*)d_out;                   // [8,512,512]

    // Idempotent; first call happens on the correctness run (outside capture).
    cudaFuncSetAttribute(mma_gemm_kernel,
                         cudaFuncAttributeMaxDynamicSharedMemorySize, SMEM_BYTES);
    cudaFuncSetAttribute(pdist_mma_kernel,
                         cudaFuncAttributeMaxDynamicSharedMemorySize, PD_SMEM);

    convertB_kernel<<<dim3(MDIM / 32, RANK / 32), dim3(32, 8)>>>(proj);
    mma_gemm_kernel<<<dim3(KSPLIT, NROWS / 64), 512, SMEM_BYTES>>>(batch);
    combine_kernel<<<NROWS * RANK / 4 / 256, 256>>>();
    pdist_mma_kernel<<<dim3(4, 4, 8), 512, PD_SMEM>>>(out);
}